// round 2
// baseline (speedup 1.0000x reference)
#include <cuda_runtime.h>

#define BB 2
#define SS 2048
#define EE 256
#define HH 32
#define DK 8

// scratch (no allocations allowed)
__device__ float g_qbuf[BB*HH*SS*DK];   // [b*H+h][s][d]  4MB
__device__ float g_ctx [BB*SS*EE];      // [b*S+s][e]     4MB

typedef unsigned long long u64;

__device__ __forceinline__ u64 pk2(float x, float y){ u64 r; asm("mov.b64 %0, {%1,%2};" : "=l"(r) : "f"(x), "f"(y)); return r; }
__device__ __forceinline__ void upk2(u64 v, float& x, float& y){ asm("mov.b64 {%0,%1}, %2;" : "=f"(x), "=f"(y) : "l"(v)); }
__device__ __forceinline__ u64 fma2_(u64 a, u64 b, u64 c){ u64 d; asm("fma.rn.f32x2 %0, %1, %2, %3;" : "=l"(d) : "l"(a), "l"(b), "l"(c)); return d; }
__device__ __forceinline__ u64 add2_(u64 a, u64 b){ u64 d; asm("add.rn.f32x2 %0, %1, %2;" : "=l"(d) : "l"(a), "l"(b)); return d; }
__device__ __forceinline__ float ex2_(float x){ float r; asm("ex2.approx.f32 %0, %1;" : "=f"(r) : "f"(x)); return r; }

// ---------------------------------------------------------------------------
// Kernel 1: q = cos(x + theta), rearranged to [b,h,s,d] contiguous
// ---------------------------------------------------------------------------
__global__ void __launch_bounds__(256) qprep_kernel(const float* __restrict__ x,
                                                    const float* __restrict__ theta)
{
    int idx = blockIdx.x * 256 + threadIdx.x;      // over B*S*E = 1,048,576
    int e  = idx & (EE-1);
    int bs = idx >> 8;           // b*S + s
    int h  = e >> 3;
    int d  = e & 7;
    int b  = bs >> 11;
    int s  = bs & (SS-1);
    float v = __cosf(x[idx] + theta[d]);
    g_qbuf[(((b*HH + h)*SS) + s)*DK + d] = v;
}

// ---------------------------------------------------------------------------
// Kernel 2: attention per head. K (=q) fully resident in smem, pair-packed.
// One thread = one query row. No running max (|score| <= 2.83).
// smem: maskbias[2048] + kT[1024][16] (pairs: kT[jp][2d+half] = K[2jp+half][d])
// ---------------------------------------------------------------------------
__global__ void __launch_bounds__(256) attn_kernel(const int* __restrict__ mask)
{
    extern __shared__ float sm[];
    float* mb = sm;          // 2048 floats: 0 or -1e9
    float* kT = sm + SS;     // 16384 floats

    const int bh  = blockIdx.y;          // b*H + h
    const int b   = bh >> 5;
    const int h   = bh & 31;
    const int tid = threadIdx.x;
    const float* qk = g_qbuf + (size_t)bh * SS * DK;

    for (int j = tid; j < SS; j += 256)
        mb[j] = (mask[b*SS + j] != 0) ? 0.0f : -1e9f;

    for (int idx = tid; idx < SS*DK; idx += 256) {
        int j = idx >> 3, d = idx & 7;
        kT[((j >> 1) << 4) + (d << 1) + (j & 1)] = qk[idx];
    }
    __syncthreads();

    const int qrow = blockIdx.x * 256 + tid;
    const float* qp = qk + qrow * DK;
    // fold log2(e)/sqrt(dk) into query
    const float QS = 1.4426950408889634f * 0.35355339059327373f;
    float4 qa = *(const float4*)qp;
    float4 qb = *(const float4*)(qp + 4);
    u64 q2[8];
    { float v;
      v = qa.x*QS; q2[0]=pk2(v,v);  v = qa.y*QS; q2[1]=pk2(v,v);
      v = qa.z*QS; q2[2]=pk2(v,v);  v = qa.w*QS; q2[3]=pk2(v,v);
      v = qb.x*QS; q2[4]=pk2(v,v);  v = qb.y*QS; q2[5]=pk2(v,v);
      v = qb.z*QS; q2[6]=pk2(v,v);  v = qb.w*QS; q2[7]=pk2(v,v); }

    u64 acc[8];
    #pragma unroll
    for (int d = 0; d < 8; ++d) acc[d] = 0ull;    // bit pattern of {0.f,0.f}
    u64 sum2 = 0ull;

    const ulonglong2* kTp = (const ulonglong2*)kT;
    const u64* mbp = (const u64*)mb;

    #pragma unroll 4
    for (int jp = 0; jp < SS/2; ++jp) {
        ulonglong2 ka = kTp[jp*4+0];
        ulonglong2 kb = kTp[jp*4+1];
        ulonglong2 kc = kTp[jp*4+2];
        ulonglong2 kd = kTp[jp*4+3];
        u64 s2 = mbp[jp];                 // additive mask bias (0 / -1e9)
        s2 = fma2_(q2[0], ka.x, s2);  s2 = fma2_(q2[1], ka.y, s2);
        s2 = fma2_(q2[2], kb.x, s2);  s2 = fma2_(q2[3], kb.y, s2);
        s2 = fma2_(q2[4], kc.x, s2);  s2 = fma2_(q2[5], kc.y, s2);
        s2 = fma2_(q2[6], kd.x, s2);  s2 = fma2_(q2[7], kd.y, s2);
        float sx, sy; upk2(s2, sx, sy);
        u64 p2 = pk2(ex2_(sx), ex2_(sy));    // exp2 of log2-domain scores
        sum2 = add2_(sum2, p2);
        acc[0] = fma2_(p2, ka.x, acc[0]);  acc[1] = fma2_(p2, ka.y, acc[1]);
        acc[2] = fma2_(p2, kb.x, acc[2]);  acc[3] = fma2_(p2, kb.y, acc[3]);
        acc[4] = fma2_(p2, kc.x, acc[4]);  acc[5] = fma2_(p2, kc.y, acc[5]);
        acc[6] = fma2_(p2, kd.x, acc[6]);  acc[7] = fma2_(p2, kd.y, acc[7]);
    }

    float slo, shi; upk2(sum2, slo, shi);
    float inv = 1.0f / (slo + shi);
    float* op = g_ctx + ((size_t)(b*SS + qrow))*EE + h*DK;
    float o[8];
    #pragma unroll
    for (int d = 0; d < 8; ++d) { float ax, ay; upk2(acc[d], ax, ay); o[d] = (ax + ay) * inv; }
    *(float4*)(op)     = make_float4(o[0], o[1], o[2], o[3]);
    *(float4*)(op + 4) = make_float4(o[4], o[5], o[6], o[7]);
}

// ---------------------------------------------------------------------------
// Kernel 3: out = ctx @ W^T + b.   ctx: [4096,256], W: [256,256] row-major.
// 64x64 tile, BK=16, 256 threads, 4x4 microtile (strided-m to avoid conflicts)
// ---------------------------------------------------------------------------
__global__ void __launch_bounds__(256) outproj_kernel(const float* __restrict__ W,
                                                      const float* __restrict__ bias,
                                                      float* __restrict__ out)
{
    __shared__ float As[16][64];
    __shared__ float Bs[16][64];
    const int tid = threadIdx.x;
    const int m0 = blockIdx.x * 64;
    const int n0 = blockIdx.y * 64;
    const int lr = tid >> 2;            // 0..63
    const int lc = (tid & 3) << 2;      // 0,4,8,12
    const int ty = tid & 15;            // m lane (strided by 16)
    const int tx = tid >> 4;            // n group (contiguous x4)

    float acc[4][4] = {};

    for (int k0 = 0; k0 < EE; k0 += 16) {
        float4 a = *(const float4*)&g_ctx[(size_t)(m0 + lr)*EE + k0 + lc];
        As[lc+0][lr] = a.x; As[lc+1][lr] = a.y; As[lc+2][lr] = a.z; As[lc+3][lr] = a.w;
        float4 w = *(const float4*)&W[(size_t)(n0 + lr)*EE + k0 + lc];
        Bs[lc+0][lr] = w.x; Bs[lc+1][lr] = w.y; Bs[lc+2][lr] = w.z; Bs[lc+3][lr] = w.w;
        __syncthreads();
        #pragma unroll
        for (int k = 0; k < 16; ++k) {
            float a0 = As[k][ty], a1 = As[k][ty+16], a2 = As[k][ty+32], a3 = As[k][ty+48];
            float4 b4 = *(const float4*)&Bs[k][tx << 2];
            acc[0][0] += a0*b4.x; acc[0][1] += a0*b4.y; acc[0][2] += a0*b4.z; acc[0][3] += a0*b4.w;
            acc[1][0] += a1*b4.x; acc[1][1] += a1*b4.y; acc[1][2] += a1*b4.z; acc[1][3] += a1*b4.w;
            acc[2][0] += a2*b4.x; acc[2][1] += a2*b4.y; acc[2][2] += a2*b4.z; acc[2][3] += a2*b4.w;
            acc[3][0] += a3*b4.x; acc[3][1] += a3*b4.y; acc[3][2] += a3*b4.z; acc[3][3] += a3*b4.w;
        }
        __syncthreads();
    }

    float4 bb = *(const float4*)&bias[n0 + (tx << 2)];
    #pragma unroll
    for (int i = 0; i < 4; ++i) {
        int row = m0 + ty + 16*i;
        float4 o;
        o.x = acc[i][0] + bb.x; o.y = acc[i][1] + bb.y;
        o.z = acc[i][2] + bb.z; o.w = acc[i][3] + bb.w;
        *(float4*)&out[(size_t)row*EE + n0 + (tx << 2)] = o;
    }
}

// ---------------------------------------------------------------------------
extern "C" void kernel_launch(void* const* d_in, const int* in_sizes, int n_in,
                              void* d_out, int out_size)
{
    const float* x     = (const float*)d_in[0];
    const int*   mask  = (const int*)  d_in[1];
    const float* theta = (const float*)d_in[2];
    const float* W_out = (const float*)d_in[3];
    const float* b_out = (const float*)d_in[4];
    float* out = (float*)d_out;

    qprep_kernel<<<(BB*SS*EE)/256, 256>>>(x, theta);

    static int smem_set = 0;
    const int smem = (SS + (SS/2)*16) * (int)sizeof(float);   // 73728
    if (!smem_set) {
        cudaFuncSetAttribute(attn_kernel, cudaFuncAttributeMaxDynamicSharedMemorySize, smem);
        smem_set = 1;
    }
    attn_kernel<<<dim3(SS/256, BB*HH), 256, smem>>>(mask);

    outproj_kernel<<<dim3((BB*SS)/64, EE/64), 256>>>(W_out, b_out, out);
}

// round 3
// speedup vs baseline: 1.0227x; 1.0227x over previous
#include <cuda_runtime.h>

#define BB 2
#define SS 2048
#define EE 256
#define HH 32
#define DK 8
#define NTILES (BB*HH*(SS/256))   // 512 work items (bh, 256-query tile)
#define GRID_ATTN (148*3)         // exactly 3 CTAs per SM

// scratch (no allocations allowed)
__device__ float g_qbuf[BB*HH*SS*DK];   // [b*H+h][s][d]  4MB
__device__ float g_ctx [BB*SS*EE];      // [b*S+s][e]     4MB
__device__ unsigned int g_tile_ctr;

typedef unsigned long long u64;

__device__ __forceinline__ u64 pk2(float x, float y){ u64 r; asm("mov.b64 %0, {%1,%2};" : "=l"(r) : "f"(x), "f"(y)); return r; }
__device__ __forceinline__ void upk2(u64 v, float& x, float& y){ asm("mov.b64 {%0,%1}, %2;" : "=f"(x), "=f"(y) : "l"(v)); }
__device__ __forceinline__ u64 fma2_(u64 a, u64 b, u64 c){ u64 d; asm("fma.rn.f32x2 %0, %1, %2, %3;" : "=l"(d) : "l"(a), "l"(b), "l"(c)); return d; }
__device__ __forceinline__ u64 add2_(u64 a, u64 b){ u64 d; asm("add.rn.f32x2 %0, %1, %2;" : "=l"(d) : "l"(a), "l"(b)); return d; }
__device__ __forceinline__ float ex2_(float x){ float r; asm("ex2.approx.f32 %0, %1;" : "=f"(r) : "f"(x)); return r; }

// ---------------------------------------------------------------------------
// Kernel 1: q = cos(x + theta), rearranged to [b,h,s,d]; also resets tile ctr
// ---------------------------------------------------------------------------
__global__ void __launch_bounds__(256) qprep_kernel(const float* __restrict__ x,
                                                    const float* __restrict__ theta)
{
    if (blockIdx.x == 0 && threadIdx.x == 0) g_tile_ctr = 0u;
    int idx = blockIdx.x * 256 + threadIdx.x;      // over B*S*E = 1,048,576
    int e  = idx & (EE-1);
    int bs = idx >> 8;           // b*S + s
    int h  = e >> 3;
    int d  = e & 7;
    int b  = bs >> 11;
    int s  = bs & (SS-1);
    float v = __cosf(x[idx] + theta[d]);
    g_qbuf[(((b*HH + h)*SS) + s)*DK + d] = v;
}

// ---------------------------------------------------------------------------
// Kernel 2: persistent work-stealing attention.
// 444 CTAs x 128 threads; each tile = (head, 256 queries); 2 queries/thread.
// K fully in smem, pair-packed. No running max (|score| <= 2.83).
// ---------------------------------------------------------------------------
__global__ void __launch_bounds__(128) attn_kernel(const int* __restrict__ mask)
{
    extern __shared__ float sm[];
    float* mb = sm;          // 2048 floats: 0 or -1e9
    float* kT = sm + SS;     // 16384 floats  kT[jp*16 + d*2 + half] = K[2jp+half][d]
    __shared__ unsigned int s_tile;

    const int tid = threadIdx.x;
    const float QS = 1.4426950408889634f * 0.35355339059327373f;  // log2e/sqrt(8)

    for (;;) {
        if (tid == 0) s_tile = atomicAdd(&g_tile_ctr, 1u);
        __syncthreads();                 // publishes s_tile; fences prior smem reads
        const unsigned int t = s_tile;
        if (t >= NTILES) return;

        const int bh = t >> 3;           // b*H + h
        const int qt = t & 7;
        const int b  = bh >> 5;
        const int h  = bh & 31;
        const float* qk = g_qbuf + (size_t)bh * SS * DK;

        // fill mask bias + pair-packed K^T
        for (int j = tid; j < SS; j += 128)
            mb[j] = (mask[b*SS + j] != 0) ? 0.0f : -1e9f;
        const float4* qk4 = (const float4*)qk;
        for (int i4 = tid; i4 < SS*DK/4; i4 += 128) {
            float4 v = qk4[i4];
            int j  = i4 >> 1;
            int d0 = (i4 & 1) << 2;
            int base = ((j >> 1) << 4) + (j & 1);
            kT[base + ((d0+0)<<1)] = v.x;
            kT[base + ((d0+1)<<1)] = v.y;
            kT[base + ((d0+2)<<1)] = v.z;
            kT[base + ((d0+3)<<1)] = v.w;
        }
        __syncthreads();

        const int qrow0 = qt*256 + tid;
        const int qrow1 = qrow0 + 128;

        u64 qA[8], qB[8];
        {
            const float4* qa = (const float4*)(qk + qrow0*DK);
            const float4* qb = (const float4*)(qk + qrow1*DK);
            float4 a0 = qa[0], a1 = qa[1], b0 = qb[0], b1 = qb[1];
            float v;
            v=a0.x*QS; qA[0]=pk2(v,v); v=a0.y*QS; qA[1]=pk2(v,v);
            v=a0.z*QS; qA[2]=pk2(v,v); v=a0.w*QS; qA[3]=pk2(v,v);
            v=a1.x*QS; qA[4]=pk2(v,v); v=a1.y*QS; qA[5]=pk2(v,v);
            v=a1.z*QS; qA[6]=pk2(v,v); v=a1.w*QS; qA[7]=pk2(v,v);
            v=b0.x*QS; qB[0]=pk2(v,v); v=b0.y*QS; qB[1]=pk2(v,v);
            v=b0.z*QS; qB[2]=pk2(v,v); v=b0.w*QS; qB[3]=pk2(v,v);
            v=b1.x*QS; qB[4]=pk2(v,v); v=b1.y*QS; qB[5]=pk2(v,v);
            v=b1.z*QS; qB[6]=pk2(v,v); v=b1.w*QS; qB[7]=pk2(v,v);
        }

        u64 accA[8], accB[8];
        #pragma unroll
        for (int d = 0; d < 8; ++d) { accA[d] = 0ull; accB[d] = 0ull; }
        u64 sumA = 0ull, sumB = 0ull;

        const ulonglong2* kTp = (const ulonglong2*)kT;
        const u64* mbp = (const u64*)mb;

        #pragma unroll 2
        for (int jp = 0; jp < SS/2; ++jp) {
            ulonglong2 ka = kTp[jp*4+0];
            ulonglong2 kb = kTp[jp*4+1];
            ulonglong2 kc = kTp[jp*4+2];
            ulonglong2 kd = kTp[jp*4+3];
            u64 m2 = mbp[jp];
            u64 sa = m2, sb = m2;
            sa = fma2_(qA[0], ka.x, sa);  sb = fma2_(qB[0], ka.x, sb);
            sa = fma2_(qA[1], ka.y, sa);  sb = fma2_(qB[1], ka.y, sb);
            sa = fma2_(qA[2], kb.x, sa);  sb = fma2_(qB[2], kb.x, sb);
            sa = fma2_(qA[3], kb.y, sa);  sb = fma2_(qB[3], kb.y, sb);
            sa = fma2_(qA[4], kc.x, sa);  sb = fma2_(qB[4], kc.x, sb);
            sa = fma2_(qA[5], kc.y, sa);  sb = fma2_(qB[5], kc.y, sb);
            sa = fma2_(qA[6], kd.x, sa);  sb = fma2_(qB[6], kd.x, sb);
            sa = fma2_(qA[7], kd.y, sa);  sb = fma2_(qB[7], kd.y, sb);
            float ax, ay, bx, by;
            upk2(sa, ax, ay);  upk2(sb, bx, by);
            u64 pa = pk2(ex2_(ax), ex2_(ay));
            u64 pb = pk2(ex2_(bx), ex2_(by));
            sumA = add2_(sumA, pa);  sumB = add2_(sumB, pb);
            accA[0] = fma2_(pa, ka.x, accA[0]);  accB[0] = fma2_(pb, ka.x, accB[0]);
            accA[1] = fma2_(pa, ka.y, accA[1]);  accB[1] = fma2_(pb, ka.y, accB[1]);
            accA[2] = fma2_(pa, kb.x, accA[2]);  accB[2] = fma2_(pb, kb.x, accB[2]);
            accA[3] = fma2_(pa, kb.y, accA[3]);  accB[3] = fma2_(pb, kb.y, accB[3]);
            accA[4] = fma2_(pa, kc.x, accA[4]);  accB[4] = fma2_(pb, kc.x, accB[4]);
            accA[5] = fma2_(pa, kc.y, accA[5]);  accB[5] = fma2_(pb, kc.y, accB[5]);
            accA[6] = fma2_(pa, kd.x, accA[6]);  accB[6] = fma2_(pb, kd.x, accB[6]);
            accA[7] = fma2_(pa, kd.y, accA[7]);  accB[7] = fma2_(pb, kd.y, accB[7]);
        }

        {
            float sl, sh;
            upk2(sumA, sl, sh);
            float inv = 1.0f / (sl + sh);
            float* op = g_ctx + ((size_t)(b*SS + qrow0))*EE + h*DK;
            float o[8];
            #pragma unroll
            for (int d = 0; d < 8; ++d) { float x1,x2; upk2(accA[d],x1,x2); o[d]=(x1+x2)*inv; }
            *(float4*)(op)     = make_float4(o[0],o[1],o[2],o[3]);
            *(float4*)(op + 4) = make_float4(o[4],o[5],o[6],o[7]);
        }
        {
            float sl, sh;
            upk2(sumB, sl, sh);
            float inv = 1.0f / (sl + sh);
            float* op = g_ctx + ((size_t)(b*SS + qrow1))*EE + h*DK;
            float o[8];
            #pragma unroll
            for (int d = 0; d < 8; ++d) { float x1,x2; upk2(accB[d],x1,x2); o[d]=(x1+x2)*inv; }
            *(float4*)(op)     = make_float4(o[0],o[1],o[2],o[3]);
            *(float4*)(op + 4) = make_float4(o[4],o[5],o[6],o[7]);
        }
    }
}

// ---------------------------------------------------------------------------
// Kernel 3: out = ctx @ W^T + b.   ctx: [4096,256], W: [256,256] row-major.
// 64x64 tile, BK=16, 256 threads, 4x4 microtile (strided-m to avoid conflicts)
// ---------------------------------------------------------------------------
__global__ void __launch_bounds__(256) outproj_kernel(const float* __restrict__ W,
                                                      const float* __restrict__ bias,
                                                      float* __restrict__ out)
{
    __shared__ float As[16][64];
    __shared__ float Bs[16][64];
    const int tid = threadIdx.x;
    const int m0 = blockIdx.x * 64;
    const int n0 = blockIdx.y * 64;
    const int lr = tid >> 2;            // 0..63
    const int lc = (tid & 3) << 2;      // 0,4,8,12
    const int ty = tid & 15;            // m lane (strided by 16)
    const int tx = tid >> 4;            // n group (contiguous x4)

    float acc[4][4] = {};

    for (int k0 = 0; k0 < EE; k0 += 16) {
        float4 a = *(const float4*)&g_ctx[(size_t)(m0 + lr)*EE + k0 + lc];
        As[lc+0][lr] = a.x; As[lc+1][lr] = a.y; As[lc+2][lr] = a.z; As[lc+3][lr] = a.w;
        float4 w = *(const float4*)&W[(size_t)(n0 + lr)*EE + k0 + lc];
        Bs[lc+0][lr] = w.x; Bs[lc+1][lr] = w.y; Bs[lc+2][lr] = w.z; Bs[lc+3][lr] = w.w;
        __syncthreads();
        #pragma unroll
        for (int k = 0; k < 16; ++k) {
            float a0 = As[k][ty], a1 = As[k][ty+16], a2 = As[k][ty+32], a3 = As[k][ty+48];
            float4 b4 = *(const float4*)&Bs[k][tx << 2];
            acc[0][0] += a0*b4.x; acc[0][1] += a0*b4.y; acc[0][2] += a0*b4.z; acc[0][3] += a0*b4.w;
            acc[1][0] += a1*b4.x; acc[1][1] += a1*b4.y; acc[1][2] += a1*b4.z; acc[1][3] += a1*b4.w;
            acc[2][0] += a2*b4.x; acc[2][1] += a2*b4.y; acc[2][2] += a2*b4.z; acc[2][3] += a2*b4.w;
            acc[3][0] += a3*b4.x; acc[3][1] += a3*b4.y; acc[3][2] += a3*b4.z; acc[3][3] += a3*b4.w;
        }
        __syncthreads();
    }

    float4 bb = *(const float4*)&bias[n0 + (tx << 2)];
    #pragma unroll
    for (int i = 0; i < 4; ++i) {
        int row = m0 + ty + 16*i;
        float4 o;
        o.x = acc[i][0] + bb.x; o.y = acc[i][1] + bb.y;
        o.z = acc[i][2] + bb.z; o.w = acc[i][3] + bb.w;
        *(float4*)&out[(size_t)row*EE + n0 + (tx << 2)] = o;
    }
}

// ---------------------------------------------------------------------------
extern "C" void kernel_launch(void* const* d_in, const int* in_sizes, int n_in,
                              void* d_out, int out_size)
{
    const float* x     = (const float*)d_in[0];
    const int*   mask  = (const int*)  d_in[1];
    const float* theta = (const float*)d_in[2];
    const float* W_out = (const float*)d_in[3];
    const float* b_out = (const float*)d_in[4];
    float* out = (float*)d_out;

    qprep_kernel<<<(BB*SS*EE)/256, 256>>>(x, theta);

    static int smem_set = 0;
    const int smem = (SS + (SS/2)*16) * (int)sizeof(float);   // 73728
    if (!smem_set) {
        cudaFuncSetAttribute(attn_kernel, cudaFuncAttributeMaxDynamicSharedMemorySize, smem);
        smem_set = 1;
    }
    attn_kernel<<<GRID_ATTN, 128, smem>>>(mask);

    outproj_kernel<<<dim3((BB*SS)/64, EE/64), 256>>>(W_out, b_out, out);
}